// round 5
// baseline (speedup 1.0000x reference)
#include <cuda_runtime.h>
#include <cstdint>

#define B_ 4
#define T_ 1024
#define E_ 512
#define H_ 64
#define DK 8

typedef unsigned long long ull;

// Scratch: attention output as A[B*T][E] rows for the combine GEMM.
__device__ float g_attn[B_ * T_ * E_];

// ---- f32x2 packed math helpers (sm_103a) ----
#define FMA2(d, a, b, c) \
    asm("fma.rn.f32x2 %0, %1, %2, %3;" : "=l"(d) : "l"(a), "l"(b), "l"(c))
#define ADD2(d, a, b) \
    asm("add.rn.f32x2 %0, %1, %2;" : "=l"(d) : "l"(a), "l"(b))
#define PACK2(d, lo, hi) \
    asm("mov.b64 %0, {%1, %2};" : "=l"(d) : "f"(lo), "f"(hi))
#define UNPACK2(lo, hi, v) \
    asm("mov.b64 {%0, %1}, %2;" : "=f"(lo), "=f"(hi) : "l"(v))

__device__ __forceinline__ float ex2_approx(float s) {
    float e;
    asm("ex2.approx.ftz.f32 %0, %1;" : "=f"(e) : "f"(s));
    return e;
}

// ============================================================================
// Kernel 1: fused proj + per-head attention.
// Grid: B*H*2 = 512 CTAs; blockIdx.x = (bh << 1) | half. 256 threads.
// Each CTA builds proj^T [8][1024] for its head in SMEM once, then each
// thread computes TWO full softmax-attention query rows (key loads + EX2
// latency amortized over 2 queries). No max-subtraction needed: |score| <= sqrt(8).
// ============================================================================
__global__ __launch_bounds__(256, 2)
void qattn_kernel(const float* __restrict__ x, const float* __restrict__ theta) {
    __shared__ __align__(16) float sT[DK * T_];   // sT[j*1024 + t]
    __shared__ float cth[DK];

    const int tid  = threadIdx.x;
    const int bid  = blockIdx.x;
    const int bh   = bid >> 1;       // 0..255
    const int half = bid & 1;
    const int b    = bh >> 6;
    const int h    = bh & 63;

    if (tid < DK) cth[tid] = __cosf(theta[tid]);
    __syncthreads();

    // Build transposed proj tile (coalesced float4 reads of x).
    const float* xb = x + ((size_t)b * T_) * E_ + h * DK;
    for (int c = tid; c < T_ * 2; c += 256) {
        int t = c >> 1;
        int hf = (c & 1) << 2;
        float4 v = *(const float4*)(xb + (size_t)t * E_ + hf);
        sT[(hf + 0) * T_ + t] = __cosf(v.x) * cth[hf + 0];
        sT[(hf + 1) * T_ + t] = __cosf(v.y) * cth[hf + 1];
        sT[(hf + 2) * T_ + t] = __cosf(v.z) * cth[hf + 2];
        sT[(hf + 3) * T_ + t] = __cosf(v.w) * cth[hf + 3];
    }
    __syncthreads();

    const int tq0 = (half << 9) + tid;   // query A
    const int tq1 = tq0 + 256;           // query B

    // Prescale q by (1/sqrt(8)) * log2(e) so scores feed ex2 directly.
    const float SC = 0.35355339059327373f * 1.4426950408889634f;
    ull qq0[DK], qq1[DK];
    #pragma unroll
    for (int j = 0; j < DK; j++) {
        float q0 = sT[j * T_ + tq0] * SC;
        float q1 = sT[j * T_ + tq1] * SC;
        PACK2(qq0[j], q0, q0);
        PACK2(qq1[j], q1, q1);
    }

    ull acc0[DK], acc1[DK];
    #pragma unroll
    for (int j = 0; j < DK; j++) { acc0[j] = 0ull; acc1[j] = 0ull; }
    ull l0 = 0ull, l1 = 0ull;

    for (int k4 = 0; k4 < T_; k4 += 4) {
        // 4 keys: one 16B broadcast load per dim.
        ull kk01[DK], kk23[DK];
        #pragma unroll
        for (int j = 0; j < DK; j++) {
            ulonglong2 kv = *(const ulonglong2*)&sT[j * T_ + k4];
            kk01[j] = kv.x;
            kk23[j] = kv.y;
        }

        // Scores: 2 chains of 4 per (query, key-pair) for ILP.
        ull sA = 0, sB = 0, sC = 0, sD = 0;
        ull tA = 0, tB = 0, tC = 0, tD = 0;
        #pragma unroll
        for (int j = 0; j < 4; j++) {
            FMA2(sA, qq0[j],     kk01[j],     sA);
            FMA2(sB, qq0[j + 4], kk01[j + 4], sB);
            FMA2(sC, qq0[j],     kk23[j],     sC);
            FMA2(sD, qq0[j + 4], kk23[j + 4], sD);
            FMA2(tA, qq1[j],     kk01[j],     tA);
            FMA2(tB, qq1[j + 4], kk01[j + 4], tB);
            FMA2(tC, qq1[j],     kk23[j],     tC);
            FMA2(tD, qq1[j + 4], kk23[j + 4], tD);
        }
        ull s01_0, s23_0, s01_1, s23_1;
        ADD2(s01_0, sA, sB);
        ADD2(s23_0, sC, sD);
        ADD2(s01_1, tA, tB);
        ADD2(s23_1, tC, tD);

        float f0, f1, f2, f3, g0, g1, g2, g3;
        UNPACK2(f0, f1, s01_0);
        UNPACK2(f2, f3, s23_0);
        UNPACK2(g0, g1, s01_1);
        UNPACK2(g2, g3, s23_1);
        f0 = ex2_approx(f0); f1 = ex2_approx(f1);
        f2 = ex2_approx(f2); f3 = ex2_approx(f3);
        g0 = ex2_approx(g0); g1 = ex2_approx(g1);
        g2 = ex2_approx(g2); g3 = ex2_approx(g3);
        ull e01_0, e23_0, e01_1, e23_1;
        PACK2(e01_0, f0, f1);
        PACK2(e23_0, f2, f3);
        PACK2(e01_1, g0, g1);
        PACK2(e23_1, g2, g3);

        ADD2(l0, l0, e01_0);
        ADD2(l1, l1, e01_1);

        #pragma unroll
        for (int j = 0; j < DK; j++) FMA2(acc0[j], e01_0, kk01[j], acc0[j]);
        #pragma unroll
        for (int j = 0; j < DK; j++) FMA2(acc1[j], e01_1, kk01[j], acc1[j]);

        ADD2(l0, l0, e23_0);
        ADD2(l1, l1, e23_1);

        #pragma unroll
        for (int j = 0; j < DK; j++) FMA2(acc0[j], e23_0, kk23[j], acc0[j]);
        #pragma unroll
        for (int j = 0; j < DK; j++) FMA2(acc1[j], e23_1, kk23[j], acc1[j]);
    }

    float la, lb;
    UNPACK2(la, lb, l0);
    float inv0 = 1.0f / (la + lb);
    UNPACK2(la, lb, l1);
    float inv1 = 1.0f / (la + lb);

    float o0[DK], o1[DK];
    #pragma unroll
    for (int j = 0; j < DK; j++) {
        float a0, a1;
        UNPACK2(a0, a1, acc0[j]);
        o0[j] = (a0 + a1) * inv0;
        UNPACK2(a0, a1, acc1[j]);
        o1[j] = (a0 + a1) * inv1;
    }

    float* p0 = g_attn + ((size_t)(b * T_ + tq0)) * E_ + h * DK;
    float* p1 = g_attn + ((size_t)(b * T_ + tq1)) * E_ + h * DK;
    *(float4*)(p0 + 0) = make_float4(o0[0], o0[1], o0[2], o0[3]);
    *(float4*)(p0 + 4) = make_float4(o0[4], o0[5], o0[6], o0[7]);
    *(float4*)(p1 + 0) = make_float4(o1[0], o1[1], o1[2], o1[3]);
    *(float4*)(p1 + 4) = make_float4(o1[4], o1[5], o1[6], o1[7]);
}

// ============================================================================
// Kernel 2: combine GEMM with f32x2. C[m,n] = sum_k A[m,k]*W[n,k] + bias[n].
// 64x64 tile, 128 threads, 8x4 microtile. A-operand pairs come packed straight
// from LDS.128 of As[k][m] (consecutive m); only w needs broadcast packs.
// ============================================================================
__global__ __launch_bounds__(128)
void combine_kernel(const float* __restrict__ W, const float* __restrict__ bias,
                    float* __restrict__ C) {
    __shared__ __align__(16) float As[16][72];   // [k][m], stride 72 keeps 16B align
    __shared__ __align__(16) float Ws[16][72];   // [k][n]

    const int tid  = threadIdx.x;
    const int col0 = blockIdx.x * 64;
    const int row0 = blockIdx.y * 64;

    const int lm  = tid >> 1;          // 0..63 (load row)
    const int lk8 = (tid & 1) << 3;    // 0 or 8 (k offset)
    const int tm  = (tid >> 4) << 3;   // 0..56 (micro rows, 8)
    const int tn  = (tid & 15) << 2;   // 0..60 (micro cols, 4)

    const float* Ap = g_attn + (size_t)(row0 + lm) * E_ + lk8;
    const float* Wp = W      + (size_t)(col0 + lm) * E_ + lk8;

    ull acc[4][4];
    #pragma unroll
    for (int i = 0; i < 4; i++)
        #pragma unroll
        for (int j = 0; j < 4; j++) acc[i][j] = 0ull;

    for (int k0 = 0; k0 < E_; k0 += 16) {
        float4 a0 = *(const float4*)(Ap + k0);
        float4 a1 = *(const float4*)(Ap + k0 + 4);
        float4 w0 = *(const float4*)(Wp + k0);
        float4 w1 = *(const float4*)(Wp + k0 + 4);
        As[lk8 + 0][lm] = a0.x; As[lk8 + 1][lm] = a0.y;
        As[lk8 + 2][lm] = a0.z; As[lk8 + 3][lm] = a0.w;
        As[lk8 + 4][lm] = a1.x; As[lk8 + 5][lm] = a1.y;
        As[lk8 + 6][lm] = a1.z; As[lk8 + 7][lm] = a1.w;
        Ws[lk8 + 0][lm] = w0.x; Ws[lk8 + 1][lm] = w0.y;
        Ws[lk8 + 2][lm] = w0.z; Ws[lk8 + 3][lm] = w0.w;
        Ws[lk8 + 4][lm] = w1.x; Ws[lk8 + 5][lm] = w1.y;
        Ws[lk8 + 6][lm] = w1.z; Ws[lk8 + 7][lm] = w1.w;
        __syncthreads();

        #pragma unroll
        for (int kk = 0; kk < 16; kk++) {
            ulonglong2 aA = *(const ulonglong2*)&As[kk][tm];      // rows (tm..tm+3)
            ulonglong2 aB = *(const ulonglong2*)&As[kk][tm + 4];  // rows (tm+4..tm+7)
            float4 w = *(const float4*)&Ws[kk][tn];
            ull w2[4];
            PACK2(w2[0], w.x, w.x);
            PACK2(w2[1], w.y, w.y);
            PACK2(w2[2], w.z, w.z);
            PACK2(w2[3], w.w, w.w);
            ull ap[4] = {aA.x, aA.y, aB.x, aB.y};
            #pragma unroll
            for (int ip = 0; ip < 4; ip++)
                #pragma unroll
                for (int j = 0; j < 4; j++)
                    FMA2(acc[ip][j], ap[ip], w2[j], acc[ip][j]);
        }
        __syncthreads();
    }

    float4 bi = *(const float4*)&bias[col0 + tn];
    const float bb[4] = {bi.x, bi.y, bi.z, bi.w};
    #pragma unroll
    for (int ip = 0; ip < 4; ip++) {
        float lo[4], hi[4];
        #pragma unroll
        for (int j = 0; j < 4; j++) UNPACK2(lo[j], hi[j], acc[ip][j]);
        int row = row0 + tm + (ip << 1);
        *(float4*)&C[(size_t)row * E_ + col0 + tn] =
            make_float4(lo[0] + bb[0], lo[1] + bb[1], lo[2] + bb[2], lo[3] + bb[3]);
        *(float4*)&C[(size_t)(row + 1) * E_ + col0 + tn] =
            make_float4(hi[0] + bb[0], hi[1] + bb[1], hi[2] + bb[2], hi[3] + bb[3]);
    }
}

extern "C" void kernel_launch(void* const* d_in, const int* in_sizes, int n_in,
                              void* d_out, int out_size) {
    const float* x     = (const float*)d_in[0];
    const float* theta = (const float*)d_in[1];
    const float* W     = (const float*)d_in[2];
    const float* bias  = (const float*)d_in[3];
    float* out = (float*)d_out;

    qattn_kernel<<<B_ * H_ * 2, 256>>>(x, theta);
    dim3 g2(E_ / 64, (B_ * T_) / 64);
    combine_kernel<<<g2, 128>>>(W, bias, out);
}

// round 6
// speedup vs baseline: 1.1631x; 1.1631x over previous
#include <cuda_runtime.h>
#include <cstdint>

#define B_ 4
#define T_ 1024
#define E_ 512
#define H_ 64
#define DK 8

typedef unsigned long long ull;

// Scratch: attention output as A[B*T][E] rows for the combine GEMM.
__device__ float g_attn[B_ * T_ * E_];

// ---- f32x2 packed math helpers (sm_103a) ----
#define FMA2(d, a, b, c) \
    asm("fma.rn.f32x2 %0, %1, %2, %3;" : "=l"(d) : "l"(a), "l"(b), "l"(c))
#define ADD2(d, a, b) \
    asm("add.rn.f32x2 %0, %1, %2;" : "=l"(d) : "l"(a), "l"(b))
#define PACK2(d, lo, hi) \
    asm("mov.b64 %0, {%1, %2};" : "=l"(d) : "f"(lo), "f"(hi))
#define UNPACK2(lo, hi, v) \
    asm("mov.b64 {%0, %1}, %2;" : "=f"(lo), "=f"(hi) : "l"(v))

__device__ __forceinline__ float ex2_approx(float s) {
    float e;
    asm("ex2.approx.ftz.f32 %0, %1;" : "=f"(e) : "f"(s));
    return e;
}

// ============================================================================
// Kernel 1: fused proj + per-head attention.
// Grid: B*H*4 = 1024 CTAs; blockIdx.x = (bh << 2) | qblock. 256 threads,
// min 3 CTAs/SM (reg cap 84; live set ~60 so no spills, 6 warps/SMSP).
// Each CTA builds proj^T [8][1024] in SMEM, then each thread computes one
// full softmax-attention query row, 2 keys per step (packed f32x2 lanes).
// No max-subtraction needed: |score| <= sqrt(8).
// ============================================================================
__global__ __launch_bounds__(256, 3)
void qattn_kernel(const float* __restrict__ x, const float* __restrict__ theta) {
    __shared__ __align__(16) float sT[DK * T_];   // sT[j*1024 + t]
    __shared__ float cth[DK];

    const int tid = threadIdx.x;
    const int bh  = blockIdx.x >> 2;   // 0..255
    const int qb  = blockIdx.x & 3;
    const int b   = bh >> 6;
    const int h   = bh & 63;

    if (tid < DK) cth[tid] = __cosf(theta[tid]);
    __syncthreads();

    // Build transposed proj tile (coalesced float4 reads of x).
    const float* xb = x + ((size_t)b * T_) * E_ + h * DK;
    for (int c = tid; c < T_ * 2; c += 256) {
        int t = c >> 1;
        int hf = (c & 1) << 2;
        float4 v = *(const float4*)(xb + (size_t)t * E_ + hf);
        sT[(hf + 0) * T_ + t] = __cosf(v.x) * cth[hf + 0];
        sT[(hf + 1) * T_ + t] = __cosf(v.y) * cth[hf + 1];
        sT[(hf + 2) * T_ + t] = __cosf(v.z) * cth[hf + 2];
        sT[(hf + 3) * T_ + t] = __cosf(v.w) * cth[hf + 3];
    }
    __syncthreads();

    const int tq = (qb << 8) + tid;

    // Prescale q by (1/sqrt(8)) * log2(e) so scores feed ex2 directly.
    const float SC = 0.35355339059327373f * 1.4426950408889634f;
    ull qq[DK];
    #pragma unroll
    for (int j = 0; j < DK; j++) {
        float q = sT[j * T_ + tq] * SC;
        PACK2(qq[j], q, q);
    }

    ull acc[DK];
    #pragma unroll
    for (int j = 0; j < DK; j++) acc[j] = 0ull;
    ull l = 0ull;

    // 2 keys per step: one LDS.64 per dim gives the packed key-pair.
    for (int k2 = 0; k2 < T_; k2 += 2) {
        ull kk[DK];
        #pragma unroll
        for (int j = 0; j < DK; j++)
            kk[j] = *(const ull*)&sT[j * T_ + k2];

        ull s = 0ull;
        #pragma unroll
        for (int j = 0; j < DK; j++)
            FMA2(s, qq[j], kk[j], s);

        float s0, s1;
        UNPACK2(s0, s1, s);
        s0 = ex2_approx(s0);
        s1 = ex2_approx(s1);
        ull e;
        PACK2(e, s0, s1);
        ADD2(l, l, e);

        #pragma unroll
        for (int j = 0; j < DK; j++)
            FMA2(acc[j], e, kk[j], acc[j]);
    }

    float la, lb;
    UNPACK2(la, lb, l);
    float inv = 1.0f / (la + lb);

    float o[DK];
    #pragma unroll
    for (int j = 0; j < DK; j++) {
        float a0, a1;
        UNPACK2(a0, a1, acc[j]);
        o[j] = (a0 + a1) * inv;
    }

    float* p = g_attn + ((size_t)(b * T_ + tq)) * E_ + h * DK;
    *(float4*)(p + 0) = make_float4(o[0], o[1], o[2], o[3]);
    *(float4*)(p + 4) = make_float4(o[4], o[5], o[6], o[7]);
}

// ============================================================================
// Kernel 2: combine GEMM with f32x2 + register-staged double buffering.
// C[m,n] = sum_k A[m,k]*W[n,k] + bias[n]. 64x64 tile, 128 threads, 8x4 micro.
// A-operand pairs come packed straight from LDS.128 of As[k][m]; next k-chunk
// LDGs are issued before the barrier so their latency hides under compute.
// ============================================================================
__global__ __launch_bounds__(128)
void combine_kernel(const float* __restrict__ W, const float* __restrict__ bias,
                    float* __restrict__ C) {
    __shared__ __align__(16) float As[16][72];   // [k][m]
    __shared__ __align__(16) float Ws[16][72];   // [k][n]

    const int tid  = threadIdx.x;
    const int col0 = blockIdx.x * 64;
    const int row0 = blockIdx.y * 64;

    const int lm  = tid >> 1;          // 0..63 (load row)
    const int lk8 = (tid & 1) << 3;    // 0 or 8 (k offset)
    const int tm  = (tid >> 4) << 3;   // 0..56 (micro rows, 8)
    const int tn  = (tid & 15) << 2;   // 0..60 (micro cols, 4)

    const float* Ap = g_attn + (size_t)(row0 + lm) * E_ + lk8;
    const float* Wp = W      + (size_t)(col0 + lm) * E_ + lk8;

    ull acc[4][4];
    #pragma unroll
    for (int i = 0; i < 4; i++)
        #pragma unroll
        for (int j = 0; j < 4; j++) acc[i][j] = 0ull;

    float4 a0 = *(const float4*)(Ap + 0);
    float4 a1 = *(const float4*)(Ap + 4);
    float4 w0 = *(const float4*)(Wp + 0);
    float4 w1 = *(const float4*)(Wp + 4);

    for (int k0 = 0; k0 < E_; k0 += 16) {
        As[lk8 + 0][lm] = a0.x; As[lk8 + 1][lm] = a0.y;
        As[lk8 + 2][lm] = a0.z; As[lk8 + 3][lm] = a0.w;
        As[lk8 + 4][lm] = a1.x; As[lk8 + 5][lm] = a1.y;
        As[lk8 + 6][lm] = a1.z; As[lk8 + 7][lm] = a1.w;
        Ws[lk8 + 0][lm] = w0.x; Ws[lk8 + 1][lm] = w0.y;
        Ws[lk8 + 2][lm] = w0.z; Ws[lk8 + 3][lm] = w0.w;
        Ws[lk8 + 4][lm] = w1.x; Ws[lk8 + 5][lm] = w1.y;
        Ws[lk8 + 6][lm] = w1.z; Ws[lk8 + 7][lm] = w1.w;

        // Prefetch next chunk BEFORE the barrier: LDG latency overlaps compute.
        if (k0 + 16 < E_) {
            a0 = *(const float4*)(Ap + k0 + 16);
            a1 = *(const float4*)(Ap + k0 + 20);
            w0 = *(const float4*)(Wp + k0 + 16);
            w1 = *(const float4*)(Wp + k0 + 20);
        }
        __syncthreads();

        #pragma unroll
        for (int kk = 0; kk < 16; kk++) {
            ulonglong2 aA = *(const ulonglong2*)&As[kk][tm];      // rows (tm..tm+3)
            ulonglong2 aB = *(const ulonglong2*)&As[kk][tm + 4];  // rows (tm+4..tm+7)
            float4 w = *(const float4*)&Ws[kk][tn];
            ull w2[4];
            PACK2(w2[0], w.x, w.x);
            PACK2(w2[1], w.y, w.y);
            PACK2(w2[2], w.z, w.z);
            PACK2(w2[3], w.w, w.w);
            ull ap[4] = {aA.x, aA.y, aB.x, aB.y};
            #pragma unroll
            for (int ip = 0; ip < 4; ip++)
                #pragma unroll
                for (int j = 0; j < 4; j++)
                    FMA2(acc[ip][j], ap[ip], w2[j], acc[ip][j]);
        }
        __syncthreads();
    }

    float4 bi = *(const float4*)&bias[col0 + tn];
    const float bb[4] = {bi.x, bi.y, bi.z, bi.w};
    #pragma unroll
    for (int ip = 0; ip < 4; ip++) {
        float lo[4], hi[4];
        #pragma unroll
        for (int j = 0; j < 4; j++) UNPACK2(lo[j], hi[j], acc[ip][j]);
        int row = row0 + tm + (ip << 1);
        *(float4*)&C[(size_t)row * E_ + col0 + tn] =
            make_float4(lo[0] + bb[0], lo[1] + bb[1], lo[2] + bb[2], lo[3] + bb[3]);
        *(float4*)&C[(size_t)(row + 1) * E_ + col0 + tn] =
            make_float4(hi[0] + bb[0], hi[1] + bb[1], hi[2] + bb[2], hi[3] + bb[3]);
    }
}

extern "C" void kernel_launch(void* const* d_in, const int* in_sizes, int n_in,
                              void* d_out, int out_size) {
    const float* x     = (const float*)d_in[0];
    const float* theta = (const float*)d_in[1];
    const float* W     = (const float*)d_in[2];
    const float* bias  = (const float*)d_in[3];
    float* out = (float*)d_out;

    qattn_kernel<<<B_ * H_ * 4, 256>>>(x, theta);
    dim3 g2(E_ / 64, (B_ * T_) / 64);
    combine_kernel<<<g2, 128>>>(W, bias, out);
}

// round 7
// speedup vs baseline: 1.1636x; 1.0004x over previous
#include <cuda_runtime.h>
#include <cstdint>

#define B_ 4
#define T_ 1024
#define E_ 512
#define H_ 64
#define DK 8

typedef unsigned long long ull;

// Scratch: attention output as A[B*T][E] rows for the combine GEMM.
__device__ float g_attn[B_ * T_ * E_];

// ---- f32x2 packed math helpers (sm_103a) ----
#define FMA2(d, a, b, c) \
    asm("fma.rn.f32x2 %0, %1, %2, %3;" : "=l"(d) : "l"(a), "l"(b), "l"(c))
#define ADD2(d, a, b) \
    asm("add.rn.f32x2 %0, %1, %2;" : "=l"(d) : "l"(a), "l"(b))
#define PACK2(d, lo, hi) \
    asm("mov.b64 %0, {%1, %2};" : "=l"(d) : "f"(lo), "f"(hi))
#define UNPACK2(lo, hi, v) \
    asm("mov.b64 {%0, %1}, %2;" : "=f"(lo), "=f"(hi) : "l"(v))

__device__ __forceinline__ float ex2_approx(float s) {
    float e;
    asm("ex2.approx.ftz.f32 %0, %1;" : "=f"(e) : "f"(s));
    return e;
}

// ============================================================================
// Kernel 1: fused proj + per-head attention.
// Grid: B*H*4 = 1024 CTAs; blockIdx.x = (bh << 2) | qblock. 256 threads,
// min 3 CTAs/SM (reg cap 84; live set ~60 so no spills, 6 warps/SMSP).
// Each CTA builds proj^T [8][1024] in SMEM, then each thread computes one
// full softmax-attention query row, 2 keys per step (packed f32x2 lanes).
// No max-subtraction needed: |score| <= sqrt(8).
// ============================================================================
__global__ __launch_bounds__(256, 3)
void qattn_kernel(const float* __restrict__ x, const float* __restrict__ theta) {
    __shared__ __align__(16) float sT[DK * T_];   // sT[j*1024 + t]
    __shared__ float cth[DK];

    const int tid = threadIdx.x;
    const int bh  = blockIdx.x >> 2;   // 0..255
    const int qb  = blockIdx.x & 3;
    const int b   = bh >> 6;
    const int h   = bh & 63;

    if (tid < DK) cth[tid] = __cosf(theta[tid]);
    __syncthreads();

    // Build transposed proj tile (coalesced float4 reads of x).
    const float* xb = x + ((size_t)b * T_) * E_ + h * DK;
    for (int c = tid; c < T_ * 2; c += 256) {
        int t = c >> 1;
        int hf = (c & 1) << 2;
        float4 v = *(const float4*)(xb + (size_t)t * E_ + hf);
        sT[(hf + 0) * T_ + t] = __cosf(v.x) * cth[hf + 0];
        sT[(hf + 1) * T_ + t] = __cosf(v.y) * cth[hf + 1];
        sT[(hf + 2) * T_ + t] = __cosf(v.z) * cth[hf + 2];
        sT[(hf + 3) * T_ + t] = __cosf(v.w) * cth[hf + 3];
    }
    __syncthreads();

    const int tq = (qb << 8) + tid;

    // Prescale q by (1/sqrt(8)) * log2(e) so scores feed ex2 directly.
    const float SC = 0.35355339059327373f * 1.4426950408889634f;
    ull qq[DK];
    #pragma unroll
    for (int j = 0; j < DK; j++) {
        float q = sT[j * T_ + tq] * SC;
        PACK2(qq[j], q, q);
    }

    ull acc[DK];
    #pragma unroll
    for (int j = 0; j < DK; j++) acc[j] = 0ull;
    ull l = 0ull;

    // 2 keys per step: one LDS.64 per dim gives the packed key-pair.
    for (int k2 = 0; k2 < T_; k2 += 2) {
        ull kk[DK];
        #pragma unroll
        for (int j = 0; j < DK; j++)
            kk[j] = *(const ull*)&sT[j * T_ + k2];

        ull s = 0ull;
        #pragma unroll
        for (int j = 0; j < DK; j++)
            FMA2(s, qq[j], kk[j], s);

        float s0, s1;
        UNPACK2(s0, s1, s);
        s0 = ex2_approx(s0);
        s1 = ex2_approx(s1);
        ull e;
        PACK2(e, s0, s1);
        ADD2(l, l, e);

        #pragma unroll
        for (int j = 0; j < DK; j++)
            FMA2(acc[j], e, kk[j], acc[j]);
    }

    float la, lb;
    UNPACK2(la, lb, l);
    float inv = 1.0f / (la + lb);

    float o[DK];
    #pragma unroll
    for (int j = 0; j < DK; j++) {
        float a0, a1;
        UNPACK2(a0, a1, acc[j]);
        o[j] = (a0 + a1) * inv;
    }

    float* p = g_attn + ((size_t)(b * T_ + tq)) * E_ + h * DK;
    *(float4*)(p + 0) = make_float4(o[0], o[1], o[2], o[3]);
    *(float4*)(p + 4) = make_float4(o[4], o[5], o[6], o[7]);
}

// ============================================================================
// Kernel 2: combine GEMM with f32x2 + register-staged double buffering.
// C[m,n] = sum_k A[m,k]*W[n,k] + bias[n]. 64x64 tile, 128 threads, 8x4 micro.
// A-operand pairs come packed straight from LDS.128 of As[k][m]; next k-chunk
// LDGs are issued before the barrier so their latency hides under compute.
// ============================================================================
__global__ __launch_bounds__(128)
void combine_kernel(const float* __restrict__ W, const float* __restrict__ bias,
                    float* __restrict__ C) {
    __shared__ __align__(16) float As[16][72];   // [k][m]
    __shared__ __align__(16) float Ws[16][72];   // [k][n]

    const int tid  = threadIdx.x;
    const int col0 = blockIdx.x * 64;
    const int row0 = blockIdx.y * 64;

    const int lm  = tid >> 1;          // 0..63 (load row)
    const int lk8 = (tid & 1) << 3;    // 0 or 8 (k offset)
    const int tm  = (tid >> 4) << 3;   // 0..56 (micro rows, 8)
    const int tn  = (tid & 15) << 2;   // 0..60 (micro cols, 4)

    const float* Ap = g_attn + (size_t)(row0 + lm) * E_ + lk8;
    const float* Wp = W      + (size_t)(col0 + lm) * E_ + lk8;

    ull acc[4][4];
    #pragma unroll
    for (int i = 0; i < 4; i++)
        #pragma unroll
        for (int j = 0; j < 4; j++) acc[i][j] = 0ull;

    float4 a0 = *(const float4*)(Ap + 0);
    float4 a1 = *(const float4*)(Ap + 4);
    float4 w0 = *(const float4*)(Wp + 0);
    float4 w1 = *(const float4*)(Wp + 4);

    for (int k0 = 0; k0 < E_; k0 += 16) {
        As[lk8 + 0][lm] = a0.x; As[lk8 + 1][lm] = a0.y;
        As[lk8 + 2][lm] = a0.z; As[lk8 + 3][lm] = a0.w;
        As[lk8 + 4][lm] = a1.x; As[lk8 + 5][lm] = a1.y;
        As[lk8 + 6][lm] = a1.z; As[lk8 + 7][lm] = a1.w;
        Ws[lk8 + 0][lm] = w0.x; Ws[lk8 + 1][lm] = w0.y;
        Ws[lk8 + 2][lm] = w0.z; Ws[lk8 + 3][lm] = w0.w;
        Ws[lk8 + 4][lm] = w1.x; Ws[lk8 + 5][lm] = w1.y;
        Ws[lk8 + 6][lm] = w1.z; Ws[lk8 + 7][lm] = w1.w;

        // Prefetch next chunk BEFORE the barrier: LDG latency overlaps compute.
        if (k0 + 16 < E_) {
            a0 = *(const float4*)(Ap + k0 + 16);
            a1 = *(const float4*)(Ap + k0 + 20);
            w0 = *(const float4*)(Wp + k0 + 16);
            w1 = *(const float4*)(Wp + k0 + 20);
        }
        __syncthreads();

        #pragma unroll
        for (int kk = 0; kk < 16; kk++) {
            ulonglong2 aA = *(const ulonglong2*)&As[kk][tm];      // rows (tm..tm+3)
            ulonglong2 aB = *(const ulonglong2*)&As[kk][tm + 4];  // rows (tm+4..tm+7)
            float4 w = *(const float4*)&Ws[kk][tn];
            ull w2[4];
            PACK2(w2[0], w.x, w.x);
            PACK2(w2[1], w.y, w.y);
            PACK2(w2[2], w.z, w.z);
            PACK2(w2[3], w.w, w.w);
            ull ap[4] = {aA.x, aA.y, aB.x, aB.y};
            #pragma unroll
            for (int ip = 0; ip < 4; ip++)
                #pragma unroll
                for (int j = 0; j < 4; j++)
                    FMA2(acc[ip][j], ap[ip], w2[j], acc[ip][j]);
        }
        __syncthreads();
    }

    float4 bi = *(const float4*)&bias[col0 + tn];
    const float bb[4] = {bi.x, bi.y, bi.z, bi.w};
    #pragma unroll
    for (int ip = 0; ip < 4; ip++) {
        float lo[4], hi[4];
        #pragma unroll
        for (int j = 0; j < 4; j++) UNPACK2(lo[j], hi[j], acc[ip][j]);
        int row = row0 + tm + (ip << 1);
        *(float4*)&C[(size_t)row * E_ + col0 + tn] =
            make_float4(lo[0] + bb[0], lo[1] + bb[1], lo[2] + bb[2], lo[3] + bb[3]);
        *(float4*)&C[(size_t)(row + 1) * E_ + col0 + tn] =
            make_float4(hi[0] + bb[0], hi[1] + bb[1], hi[2] + bb[2], hi[3] + bb[3]);
    }
}

extern "C" void kernel_launch(void* const* d_in, const int* in_sizes, int n_in,
                              void* d_out, int out_size) {
    const float* x     = (const float*)d_in[0];
    const float* theta = (const float*)d_in[1];
    const float* W     = (const float*)d_in[2];
    const float* bias  = (const float*)d_in[3];
    float* out = (float*)d_out;

    qattn_kernel<<<B_ * H_ * 4, 256>>>(x, theta);
    dim3 g2(E_ / 64, (B_ * T_) / 64);
    combine_kernel<<<g2, 128>>>(W, bias, out);
}

// round 8
// speedup vs baseline: 2.1652x; 1.8607x over previous
#include <cuda_runtime.h>
#include <cuda_bf16.h>
#include <cstdint>

#define B_ 4
#define T_ 1024
#define E_ 512
#define H_ 64
#define DK 8

typedef unsigned long long ull;

__device__ float g_attn[B_ * T_ * E_];

#define FMA2(d, a, b, c) \
    asm("fma.rn.f32x2 %0, %1, %2, %3;" : "=l"(d) : "l"(a), "l"(b), "l"(c))
#define PACK2(d, lo, hi) \
    asm("mov.b64 %0, {%1, %2};" : "=l"(d) : "f"(lo), "f"(hi))
#define UNPACK2(lo, hi, v) \
    asm("mov.b64 {%0, %1}, %2;" : "=f"(lo), "=f"(hi) : "l"(v))

__device__ __forceinline__ float ex2_approx(float s) {
    float e;
    asm("ex2.approx.ftz.f32 %0, %1;" : "=f"(e) : "f"(s));
    return e;
}
// pack two f32 -> bf16x2, lo = first arg (element 0 = low half)
__device__ __forceinline__ uint32_t bf2(float lo, float hi) {
    uint32_t r;
    asm("cvt.rn.bf16x2.f32 %0, %1, %2;" : "=r"(r) : "f"(hi), "f"(lo));
    return r;
}
__device__ __forceinline__ uint32_t smem_u32(const void* p) {
    uint32_t a;
    asm("{ .reg .u64 t; cvta.to.shared.u64 t, %1; cvt.u32.u64 %0, t; }" : "=r"(a) : "l"(p));
    return a;
}
__device__ __forceinline__ void ldsm_x2(uint32_t& r0, uint32_t& r1, uint32_t a) {
    asm volatile("ldmatrix.sync.aligned.m8n8.x2.shared.b16 {%0,%1}, [%2];"
                 : "=r"(r0), "=r"(r1) : "r"(a));
}
__device__ __forceinline__ void ldsm_x2t(uint32_t& r0, uint32_t& r1, uint32_t a) {
    asm volatile("ldmatrix.sync.aligned.m8n8.x2.trans.shared.b16 {%0,%1}, [%2];"
                 : "=r"(r0), "=r"(r1) : "r"(a));
}
__device__ __forceinline__ void mma_k8(float c[4], uint32_t a0, uint32_t a1, uint32_t b0) {
    asm volatile("mma.sync.aligned.m16n8k8.row.col.f32.bf16.bf16.f32 "
                 "{%0,%1,%2,%3}, {%4,%5}, {%6}, {%0,%1,%2,%3};"
                 : "+f"(c[0]), "+f"(c[1]), "+f"(c[2]), "+f"(c[3])
                 : "r"(a0), "r"(a1), "r"(b0));
}
__device__ __forceinline__ void mma_k16(float c[4], uint32_t a0, uint32_t a1,
                                        uint32_t a2, uint32_t a3,
                                        uint32_t b0, uint32_t b1) {
    asm volatile("mma.sync.aligned.m16n8k16.row.col.f32.bf16.bf16.f32 "
                 "{%0,%1,%2,%3}, {%4,%5,%6,%7}, {%8,%9}, {%0,%1,%2,%3};"
                 : "+f"(c[0]), "+f"(c[1]), "+f"(c[2]), "+f"(c[3])
                 : "r"(a0), "r"(a1), "r"(a2), "r"(a3), "r"(b0), "r"(b1));
}

// ============================================================================
// Kernel 1: tensor-core attention via mma.sync. Grid = B*H*8 = 2048 CTAs,
// 256 threads (8 warps). Warp w handles 16 queries of the CTA's 128-q tile.
// Ps = sqrt(scale*log2e)-scaled bf16 proj (S operandi, symmetric scale),
// Pv = unscaled bf16 proj (values). S-accum C-frags repack directly into the
// PV A-frag (FA2 identity). No softmax max needed: |score| <= sqrt(8).
// ============================================================================
__global__ __launch_bounds__(256)
void qattn_mma(const float* __restrict__ x, const float* __restrict__ theta) {
    __shared__ __align__(16) __nv_bfloat16 Ps[T_][DK];   // 16KB
    __shared__ __align__(16) __nv_bfloat16 Pv[T_][DK];   // 16KB
    __shared__ float cth[DK];

    const int tid  = threadIdx.x;
    const int lane = tid & 31;
    const int warp = tid >> 5;
    const int qt   = blockIdx.x & 7;
    const int bh   = blockIdx.x >> 3;
    const int b    = bh >> 6;
    const int h    = bh & 63;

    if (tid < DK) cth[tid] = __cosf(theta[tid]);
    __syncthreads();

    const float S1 = 0.714215694f;  // sqrt((1/sqrt(8)) * log2(e))
    const float* xb = x + ((size_t)b * T_) * E_ + h * DK;
    #pragma unroll
    for (int i = 0; i < 4; i++) {
        int t = i * 256 + tid;
        float4 v0 = *(const float4*)(xb + (size_t)t * E_);
        float4 v1 = *(const float4*)(xb + (size_t)t * E_ + 4);
        float c[8];
        c[0] = __cosf(v0.x) * cth[0]; c[1] = __cosf(v0.y) * cth[1];
        c[2] = __cosf(v0.z) * cth[2]; c[3] = __cosf(v0.w) * cth[3];
        c[4] = __cosf(v1.x) * cth[4]; c[5] = __cosf(v1.y) * cth[5];
        c[6] = __cosf(v1.z) * cth[6]; c[7] = __cosf(v1.w) * cth[7];
        uint4 ps, pv;
        ps.x = bf2(S1 * c[0], S1 * c[1]); ps.y = bf2(S1 * c[2], S1 * c[3]);
        ps.z = bf2(S1 * c[4], S1 * c[5]); ps.w = bf2(S1 * c[6], S1 * c[7]);
        pv.x = bf2(c[0], c[1]); pv.y = bf2(c[2], c[3]);
        pv.z = bf2(c[4], c[5]); pv.w = bf2(c[6], c[7]);
        *(uint4*)&Ps[t][0] = ps;
        *(uint4*)&Pv[t][0] = pv;
    }
    __syncthreads();

    // Q A-fragment (m16n8k8): rows qbase..qbase+15 of Ps.
    const int qbase = qt * 128 + warp * 16;
    uint32_t qa0, qa1;
    ldsm_x2(qa0, qa1, smem_u32(&Ps[qbase + (lane & 15)][0]));

    float o[4] = {0.f, 0.f, 0.f, 0.f};
    float l0 = 0.f, l1 = 0.f;

    for (int k0 = 0; k0 < T_; k0 += 16) {
        uint32_t kb0, kb1, vb0, vb1;
        ldsm_x2(kb0, kb1, smem_u32(&Ps[k0 + (lane & 15)][0]));
        ldsm_x2t(vb0, vb1, smem_u32(&Pv[k0 + (lane & 15)][0]));

        float c0[4] = {0.f, 0.f, 0.f, 0.f};
        float c1[4] = {0.f, 0.f, 0.f, 0.f};
        mma_k8(c0, qa0, qa1, kb0);   // keys k0..k0+7
        mma_k8(c1, qa0, qa1, kb1);   // keys k0+8..k0+15

        float e00 = ex2_approx(c0[0]), e01 = ex2_approx(c0[1]);
        float e02 = ex2_approx(c0[2]), e03 = ex2_approx(c0[3]);
        float e10 = ex2_approx(c1[0]), e11 = ex2_approx(c1[1]);
        float e12 = ex2_approx(c1[2]), e13 = ex2_approx(c1[3]);
        l0 += (e00 + e01) + (e10 + e11);   // row r = lane/4
        l1 += (e02 + e03) + (e12 + e13);   // row r + 8

        // P A-frag (16x16): a0=(r,c0..1) a1=(r+8) a2=(r,c+8) a3=(r+8,c+8)
        uint32_t p0 = bf2(e00, e01), p1 = bf2(e02, e03);
        uint32_t p2 = bf2(e10, e11), p3 = bf2(e12, e13);
        mma_k16(o, p0, p1, p2, p3, vb0, vb1);
    }

    // Row sums across the 4 lanes sharing a row.
    l0 += __shfl_xor_sync(0xFFFFFFFFu, l0, 1);
    l0 += __shfl_xor_sync(0xFFFFFFFFu, l0, 2);
    l1 += __shfl_xor_sync(0xFFFFFFFFu, l1, 1);
    l1 += __shfl_xor_sync(0xFFFFFFFFu, l1, 2);
    float inv0 = 1.0f / l0, inv1 = 1.0f / l1;

    const int q0 = qbase + (lane >> 2);
    const int col = h * DK + ((lane & 3) << 1);
    float* p0 = g_attn + ((size_t)(b * T_ + q0)) * E_ + col;
    float* p1 = g_attn + ((size_t)(b * T_ + q0 + 8)) * E_ + col;
    *(float2*)p0 = make_float2(o[0] * inv0, o[1] * inv0);
    *(float2*)p1 = make_float2(o[2] * inv1, o[3] * inv1);
}

// ============================================================================
// Kernel 2: combine GEMM (R6 best: 64.7us). f32x2 + register double buffering.
// ============================================================================
__global__ __launch_bounds__(128)
void combine_kernel(const float* __restrict__ W, const float* __restrict__ bias,
                    float* __restrict__ C) {
    __shared__ __align__(16) float As[16][72];
    __shared__ __align__(16) float Ws[16][72];

    const int tid  = threadIdx.x;
    const int col0 = blockIdx.x * 64;
    const int row0 = blockIdx.y * 64;
    const int lm  = tid >> 1;
    const int lk8 = (tid & 1) << 3;
    const int tm  = (tid >> 4) << 3;
    const int tn  = (tid & 15) << 2;

    const float* Ap = g_attn + (size_t)(row0 + lm) * E_ + lk8;
    const float* Wp = W      + (size_t)(col0 + lm) * E_ + lk8;

    ull acc[4][4];
    #pragma unroll
    for (int i = 0; i < 4; i++)
        #pragma unroll
        for (int j = 0; j < 4; j++) acc[i][j] = 0ull;

    float4 a0 = *(const float4*)(Ap + 0);
    float4 a1 = *(const float4*)(Ap + 4);
    float4 w0 = *(const float4*)(Wp + 0);
    float4 w1 = *(const float4*)(Wp + 4);

    for (int k0 = 0; k0 < E_; k0 += 16) {
        As[lk8 + 0][lm] = a0.x; As[lk8 + 1][lm] = a0.y;
        As[lk8 + 2][lm] = a0.z; As[lk8 + 3][lm] = a0.w;
        As[lk8 + 4][lm] = a1.x; As[lk8 + 5][lm] = a1.y;
        As[lk8 + 6][lm] = a1.z; As[lk8 + 7][lm] = a1.w;
        Ws[lk8 + 0][lm] = w0.x; Ws[lk8 + 1][lm] = w0.y;
        Ws[lk8 + 2][lm] = w0.z; Ws[lk8 + 3][lm] = w0.w;
        Ws[lk8 + 4][lm] = w1.x; Ws[lk8 + 5][lm] = w1.y;
        Ws[lk8 + 6][lm] = w1.z; Ws[lk8 + 7][lm] = w1.w;
        if (k0 + 16 < E_) {
            a0 = *(const float4*)(Ap + k0 + 16);
            a1 = *(const float4*)(Ap + k0 + 20);
            w0 = *(const float4*)(Wp + k0 + 16);
            w1 = *(const float4*)(Wp + k0 + 20);
        }
        __syncthreads();
        #pragma unroll
        for (int kk = 0; kk < 16; kk++) {
            ulonglong2 aA = *(const ulonglong2*)&As[kk][tm];
            ulonglong2 aB = *(const ulonglong2*)&As[kk][tm + 4];
            float4 w = *(const float4*)&Ws[kk][tn];
            ull w2[4];
            PACK2(w2[0], w.x, w.x);
            PACK2(w2[1], w.y, w.y);
            PACK2(w2[2], w.z, w.z);
            PACK2(w2[3], w.w, w.w);
            ull ap[4] = {aA.x, aA.y, aB.x, aB.y};
            #pragma unroll
            for (int ip = 0; ip < 4; ip++)
                #pragma unroll
                for (int j = 0; j < 4; j++)
                    FMA2(acc[ip][j], ap[ip], w2[j], acc[ip][j]);
        }
        __syncthreads();
    }

    float4 bi = *(const float4*)&bias[col0 + tn];
    const float bb[4] = {bi.x, bi.y, bi.z, bi.w};
    #pragma unroll
    for (int ip = 0; ip < 4; ip++) {
        float lo[4], hi[4];
        #pragma unroll
        for (int j = 0; j < 4; j++) UNPACK2(lo[j], hi[j], acc[ip][j]);
        int row = row0 + tm + (ip << 1);
        *(float4*)&C[(size_t)row * E_ + col0 + tn] =
            make_float4(lo[0] + bb[0], lo[1] + bb[1], lo[2] + bb[2], lo[3] + bb[3]);
        *(float4*)&C[(size_t)(row + 1) * E_ + col0 + tn] =
            make_float4(hi[0] + bb[0], hi[1] + bb[1], hi[2] + bb[2], hi[3] + bb[3]);
    }
}

extern "C" void kernel_launch(void* const* d_in, const int* in_sizes, int n_in,
                              void* d_out, int out_size) {
    const float* x     = (const float*)d_in[0];
    const float* theta = (const float*)d_in[1];
    const float* W     = (const float*)d_in[2];
    const float* bias  = (const float*)d_in[3];
    float* out = (float*)d_out;

    qattn_mma<<<B_ * H_ * 8, 256>>>(x, theta);
    dim3 g2(E_ / 64, (B_ * T_) / 64);
    combine_kernel<<<g2, 128>>>(W, bias, out);
}

// round 9
// speedup vs baseline: 2.8905x; 1.3350x over previous
#include <cuda_runtime.h>
#include <cuda_bf16.h>
#include <cstdint>

#define B_ 4
#define T_ 1024
#define E_ 512
#define H_ 64
#define DK 8

typedef unsigned long long ull;

__device__ float g_attn[B_ * T_ * E_];

__device__ __forceinline__ float ex2_approx(float s) {
    float e;
    asm("ex2.approx.ftz.f32 %0, %1;" : "=f"(e) : "f"(s));
    return e;
}
__device__ __forceinline__ uint32_t bf2(float lo, float hi) {
    uint32_t r;
    asm("cvt.rn.bf16x2.f32 %0, %1, %2;" : "=r"(r) : "f"(hi), "f"(lo));
    return r;
}
__device__ __forceinline__ uint32_t tf32r(float f) {
    uint32_t u;
    asm("cvt.rna.tf32.f32 %0, %1;" : "=r"(u) : "f"(f));
    return u;
}
__device__ __forceinline__ uint32_t smem_u32(const void* p) {
    uint32_t a;
    asm("{ .reg .u64 t; cvta.to.shared.u64 t, %1; cvt.u32.u64 %0, t; }" : "=r"(a) : "l"(p));
    return a;
}
__device__ __forceinline__ void ldsm_x2(uint32_t& r0, uint32_t& r1, uint32_t a) {
    asm volatile("ldmatrix.sync.aligned.m8n8.x2.shared.b16 {%0,%1}, [%2];"
                 : "=r"(r0), "=r"(r1) : "r"(a));
}
__device__ __forceinline__ void ldsm_x2t(uint32_t& r0, uint32_t& r1, uint32_t a) {
    asm volatile("ldmatrix.sync.aligned.m8n8.x2.trans.shared.b16 {%0,%1}, [%2];"
                 : "=r"(r0), "=r"(r1) : "r"(a));
}
__device__ __forceinline__ void mma_k8(float c[4], uint32_t a0, uint32_t a1, uint32_t b0) {
    asm volatile("mma.sync.aligned.m16n8k8.row.col.f32.bf16.bf16.f32 "
                 "{%0,%1,%2,%3}, {%4,%5}, {%6}, {%0,%1,%2,%3};"
                 : "+f"(c[0]), "+f"(c[1]), "+f"(c[2]), "+f"(c[3])
                 : "r"(a0), "r"(a1), "r"(b0));
}
__device__ __forceinline__ void mma_k16(float c[4], uint32_t a0, uint32_t a1,
                                        uint32_t a2, uint32_t a3,
                                        uint32_t b0, uint32_t b1) {
    asm volatile("mma.sync.aligned.m16n8k16.row.col.f32.bf16.bf16.f32 "
                 "{%0,%1,%2,%3}, {%4,%5,%6,%7}, {%8,%9}, {%0,%1,%2,%3};"
                 : "+f"(c[0]), "+f"(c[1]), "+f"(c[2]), "+f"(c[3])
                 : "r"(a0), "r"(a1), "r"(a2), "r"(a3), "r"(b0), "r"(b1));
}
__device__ __forceinline__ void mma_tf32(float c[4], uint32_t a0, uint32_t a1,
                                         uint32_t a2, uint32_t a3,
                                         uint32_t b0, uint32_t b1) {
    asm volatile("mma.sync.aligned.m16n8k8.row.col.f32.tf32.tf32.f32 "
                 "{%0,%1,%2,%3}, {%4,%5,%6,%7}, {%8,%9}, {%0,%1,%2,%3};"
                 : "+f"(c[0]), "+f"(c[1]), "+f"(c[2]), "+f"(c[3])
                 : "r"(a0), "r"(a1), "r"(a2), "r"(a3), "r"(b0), "r"(b1));
}

// ============================================================================
// Kernel 1: tensor-core attention via mma.sync (unchanged from R8, ~56us,
// at the EX2/MUFU floor). Grid = B*H*8 = 2048 CTAs, 256 threads.
// ============================================================================
__global__ __launch_bounds__(256)
void qattn_mma(const float* __restrict__ x, const float* __restrict__ theta) {
    __shared__ __align__(16) __nv_bfloat16 Ps[T_][DK];
    __shared__ __align__(16) __nv_bfloat16 Pv[T_][DK];
    __shared__ float cth[DK];

    const int tid  = threadIdx.x;
    const int lane = tid & 31;
    const int warp = tid >> 5;
    const int qt   = blockIdx.x & 7;
    const int bh   = blockIdx.x >> 3;
    const int b    = bh >> 6;
    const int h    = bh & 63;

    if (tid < DK) cth[tid] = __cosf(theta[tid]);
    __syncthreads();

    const float S1 = 0.714215694f;  // sqrt((1/sqrt(8)) * log2(e))
    const float* xb = x + ((size_t)b * T_) * E_ + h * DK;
    #pragma unroll
    for (int i = 0; i < 4; i++) {
        int t = i * 256 + tid;
        float4 v0 = *(const float4*)(xb + (size_t)t * E_);
        float4 v1 = *(const float4*)(xb + (size_t)t * E_ + 4);
        float c[8];
        c[0] = __cosf(v0.x) * cth[0]; c[1] = __cosf(v0.y) * cth[1];
        c[2] = __cosf(v0.z) * cth[2]; c[3] = __cosf(v0.w) * cth[3];
        c[4] = __cosf(v1.x) * cth[4]; c[5] = __cosf(v1.y) * cth[5];
        c[6] = __cosf(v1.z) * cth[6]; c[7] = __cosf(v1.w) * cth[7];
        uint4 ps, pv;
        ps.x = bf2(S1 * c[0], S1 * c[1]); ps.y = bf2(S1 * c[2], S1 * c[3]);
        ps.z = bf2(S1 * c[4], S1 * c[5]); ps.w = bf2(S1 * c[6], S1 * c[7]);
        pv.x = bf2(c[0], c[1]); pv.y = bf2(c[2], c[3]);
        pv.z = bf2(c[4], c[5]); pv.w = bf2(c[6], c[7]);
        *(uint4*)&Ps[t][0] = ps;
        *(uint4*)&Pv[t][0] = pv;
    }
    __syncthreads();

    const int qbase = qt * 128 + warp * 16;
    uint32_t qa0, qa1;
    ldsm_x2(qa0, qa1, smem_u32(&Ps[qbase + (lane & 15)][0]));

    float o[4] = {0.f, 0.f, 0.f, 0.f};
    float l0 = 0.f, l1 = 0.f;

    for (int k0 = 0; k0 < T_; k0 += 16) {
        uint32_t kb0, kb1, vb0, vb1;
        ldsm_x2(kb0, kb1, smem_u32(&Ps[k0 + (lane & 15)][0]));
        ldsm_x2t(vb0, vb1, smem_u32(&Pv[k0 + (lane & 15)][0]));

        float c0[4] = {0.f, 0.f, 0.f, 0.f};
        float c1[4] = {0.f, 0.f, 0.f, 0.f};
        mma_k8(c0, qa0, qa1, kb0);
        mma_k8(c1, qa0, qa1, kb1);

        float e00 = ex2_approx(c0[0]), e01 = ex2_approx(c0[1]);
        float e02 = ex2_approx(c0[2]), e03 = ex2_approx(c0[3]);
        float e10 = ex2_approx(c1[0]), e11 = ex2_approx(c1[1]);
        float e12 = ex2_approx(c1[2]), e13 = ex2_approx(c1[3]);
        l0 += (e00 + e01) + (e10 + e11);
        l1 += (e02 + e03) + (e12 + e13);

        uint32_t p0 = bf2(e00, e01), p1 = bf2(e02, e03);
        uint32_t p2 = bf2(e10, e11), p3 = bf2(e12, e13);
        mma_k16(o, p0, p1, p2, p3, vb0, vb1);
    }

    l0 += __shfl_xor_sync(0xFFFFFFFFu, l0, 1);
    l0 += __shfl_xor_sync(0xFFFFFFFFu, l0, 2);
    l1 += __shfl_xor_sync(0xFFFFFFFFu, l1, 1);
    l1 += __shfl_xor_sync(0xFFFFFFFFu, l1, 2);
    float inv0 = 1.0f / l0, inv1 = 1.0f / l1;

    const int q0 = qbase + (lane >> 2);
    const int col = h * DK + ((lane & 3) << 1);
    float* p0 = g_attn + ((size_t)(b * T_ + q0)) * E_ + col;
    float* p1 = g_attn + ((size_t)(b * T_ + q0 + 8)) * E_ + col;
    *(float2*)p0 = make_float2(o[0] * inv0, o[1] * inv0);
    *(float2*)p1 = make_float2(o[2] * inv1, o[3] * inv1);
}

// ============================================================================
// Kernel 2: combine GEMM via tf32 mma.sync. C = A[4096x512] . W[512x512]^T + b.
// CTA: 128m x 64n tile, 256 threads, 8 warps in 4x2 grid; warp = 32x32
// (2 m-frags x 4 n-frags of m16n8k8). tf32 (cvt.rna) keeps rel_err ~2e-4.
// As/Ws stride 20 floats -> conflict-free fragment reads. Register prefetch.
// ============================================================================
__global__ __launch_bounds__(256)
void combine_tf32(const float* __restrict__ W, const float* __restrict__ bias,
                  float* __restrict__ C) {
    __shared__ uint32_t As[128][20];
    __shared__ uint32_t Ws[64][20];

    const int tid  = threadIdx.x;
    const int lane = tid & 31;
    const int warp = tid >> 5;
    const int g    = lane >> 2;     // groupID
    const int tg   = lane & 3;      // thread-in-group
    const int row0 = blockIdx.y * 128;
    const int col0 = blockIdx.x * 64;
    const int mb   = (warp >> 1) * 32;   // warp m offset
    const int nb   = (warp & 1) * 32;    // warp n offset

    // Load mapping: A: row=tid>>1 (0..127), k-block = (tid&1)*8 (two float4s).
    //               W: row=tid>>2 (0..63),  k-block = (tid&3)*4 (one float4).
    const int ar = tid >> 1, ak = (tid & 1) << 3;
    const int wr = tid >> 2, wk = (tid & 3) << 2;
    const float* Ap = g_attn + (size_t)(row0 + ar) * E_ + ak;
    const float* Wp = W      + (size_t)(col0 + wr) * E_ + wk;

    float acc[2][4][4];
    #pragma unroll
    for (int mi = 0; mi < 2; mi++)
        #pragma unroll
        for (int ni = 0; ni < 4; ni++)
            #pragma unroll
            for (int j = 0; j < 4; j++) acc[mi][ni][j] = 0.f;

    float4 ra0 = *(const float4*)(Ap);
    float4 ra1 = *(const float4*)(Ap + 4);
    float4 rw  = *(const float4*)(Wp);

    for (int k0 = 0; k0 < E_; k0 += 16) {
        As[ar][ak + 0] = tf32r(ra0.x); As[ar][ak + 1] = tf32r(ra0.y);
        As[ar][ak + 2] = tf32r(ra0.z); As[ar][ak + 3] = tf32r(ra0.w);
        As[ar][ak + 4] = tf32r(ra1.x); As[ar][ak + 5] = tf32r(ra1.y);
        As[ar][ak + 6] = tf32r(ra1.z); As[ar][ak + 7] = tf32r(ra1.w);
        Ws[wr][wk + 0] = tf32r(rw.x);  Ws[wr][wk + 1] = tf32r(rw.y);
        Ws[wr][wk + 2] = tf32r(rw.z);  Ws[wr][wk + 3] = tf32r(rw.w);

        if (k0 + 16 < E_) {
            ra0 = *(const float4*)(Ap + k0 + 16);
            ra1 = *(const float4*)(Ap + k0 + 20);
            rw  = *(const float4*)(Wp + k0 + 16);
        }
        __syncthreads();

        #pragma unroll
        for (int s = 0; s < 16; s += 8) {
            uint32_t a[2][4];
            #pragma unroll
            for (int mi = 0; mi < 2; mi++) {
                int r = mb + mi * 16 + g;
                a[mi][0] = As[r][s + tg];
                a[mi][1] = As[r + 8][s + tg];
                a[mi][2] = As[r][s + tg + 4];
                a[mi][3] = As[r + 8][s + tg + 4];
            }
            #pragma unroll
            for (int ni = 0; ni < 4; ni++) {
                int n = nb + ni * 8 + g;
                uint32_t b0 = Ws[n][s + tg];
                uint32_t b1 = Ws[n][s + tg + 4];
                mma_tf32(acc[0][ni], a[0][0], a[0][1], a[0][2], a[0][3], b0, b1);
                mma_tf32(acc[1][ni], a[1][0], a[1][1], a[1][2], a[1][3], b0, b1);
            }
        }
        __syncthreads();
    }

    #pragma unroll
    for (int mi = 0; mi < 2; mi++) {
        int row = row0 + mb + mi * 16 + g;
        #pragma unroll
        for (int ni = 0; ni < 4; ni++) {
            int c = col0 + nb + ni * 8 + (tg << 1);
            float2 bi = *(const float2*)&bias[c];
            *(float2*)&C[(size_t)row * E_ + c] =
                make_float2(acc[mi][ni][0] + bi.x, acc[mi][ni][1] + bi.y);
            *(float2*)&C[(size_t)(row + 8) * E_ + c] =
                make_float2(acc[mi][ni][2] + bi.x, acc[mi][ni][3] + bi.y);
        }
    }
}

extern "C" void kernel_launch(void* const* d_in, const int* in_sizes, int n_in,
                              void* d_out, int out_size) {
    const float* x     = (const float*)d_in[0];
    const float* theta = (const float*)d_in[1];
    const float* W     = (const float*)d_in[2];
    const float* bias  = (const float*)d_in[3];
    float* out = (float*)d_out;

    qattn_mma<<<B_ * H_ * 8, 256>>>(x, theta);
    dim3 g2(E_ / 64, (B_ * T_) / 128);
    combine_tf32<<<g2, 256>>>(W, bias, out);
}